// round 1
// baseline (speedup 1.0000x reference)
#include <cuda_runtime.h>
#include <math.h>

#define BB 64
#define CC 768
#define C2 1536
#define RR 96
#define EE 16

// ---- scratch (device globals; no allocations allowed) ----
__device__ float d_gT[CC * BB];    // pooled, transposed [C][B]
__device__ float d_h1T[C2 * BB];   // after conv1+BN+GELU, [2C][B]
__device__ float d_aT[RR * BB];    // CA bottleneck, [R][B]
__device__ float d_h2T[C2 * BB];   // after gating, [2C][B]
__device__ float d_h3[BB * CC];    // after conv2+BN+GELU, [B][C] (B-major for scores)

__device__ __forceinline__ float gelu_exact(float z) {
    return 0.5f * z * (1.0f + erff(z * 0.7071067811865476f));
}

// ---- kernel 1: global average pool, x[B,C,H,W] -> gT[C][B] ----
// one warp per (b,c) row of 1024 floats; 8 x float4 per lane.
__global__ __launch_bounds__(256) void pool_kernel(const float4* __restrict__ x) {
    int gid  = blockIdx.x * 256 + threadIdx.x;
    int warp = gid >> 5;
    int lane = gid & 31;
    const float4* p = x + (size_t)warp * 256 + lane;
    float s = 0.f;
#pragma unroll
    for (int k = 0; k < 8; k++) {
        float4 v = p[32 * k];
        s += (v.x + v.y) + (v.z + v.w);
    }
#pragma unroll
    for (int o = 16; o; o >>= 1) s += __shfl_xor_sync(0xffffffffu, s, o);
    if (lane == 0) {
        int b = warp / CC;
        int c = warp - b * CC;
        d_gT[c * BB + b] = s * (1.0f / 1024.0f);
    }
}

// ---- kernel 2: h1 = GELU(BN(g @ w1^T + b1)), out [2C][B] ----
// block = (64 b, 4 ty); each thread computes 4 output channels.
__global__ __launch_bounds__(256) void gemm1_kernel(
    const float* __restrict__ w1, const float* __restrict__ b1,
    const float* __restrict__ bg, const float* __restrict__ bb,
    const float* __restrict__ bm, const float* __restrict__ bv) {
    int b  = threadIdx.x;
    int j0 = blockIdx.x * 16 + threadIdx.y * 4;
    const float* w = w1 + (size_t)j0 * CC;
    float acc[4] = {0.f, 0.f, 0.f, 0.f};
#pragma unroll 4
    for (int k = 0; k < CC; k++) {
        float gv = d_gT[k * BB + b];
#pragma unroll
        for (int q = 0; q < 4; q++)
            acc[q] = fmaf(gv, w[q * CC + k], acc[q]);
    }
#pragma unroll
    for (int q = 0; q < 4; q++) {
        int j = j0 + q;
        float y = acc[q] + b1[j];
        y = (y - bm[j]) * rsqrtf(bv[j] + 1e-5f) * bg[j] + bb[j];
        d_h1T[j * BB + b] = gelu_exact(y);
    }
}

// ---- kernel 3: a = GELU(h1 @ caw1^T + cab1), out [R][B] ----
__global__ __launch_bounds__(256) void ca1_kernel(
    const float* __restrict__ caw1, const float* __restrict__ cab1) {
    int b  = threadIdx.x;
    int j0 = blockIdx.x * 16 + threadIdx.y * 4;
    const float* w = caw1 + (size_t)j0 * C2;
    float acc[4] = {0.f, 0.f, 0.f, 0.f};
#pragma unroll 4
    for (int k = 0; k < C2; k++) {
        float hv = d_h1T[k * BB + b];
#pragma unroll
        for (int q = 0; q < 4; q++)
            acc[q] = fmaf(hv, w[q * C2 + k], acc[q]);
    }
#pragma unroll
    for (int q = 0; q < 4; q++) {
        int j = j0 + q;
        d_aT[j * BB + b] = gelu_exact(acc[q] + cab1[j]);
    }
}

// ---- kernel 4: z = a @ caw2^T + cab2 ; h2 = h1 * sigmoid(2z), out [2C][B] ----
__global__ __launch_bounds__(256) void ca2_kernel(
    const float* __restrict__ caw2, const float* __restrict__ cab2) {
    int b  = threadIdx.x;
    int j0 = blockIdx.x * 16 + threadIdx.y * 4;
    const float* w = caw2 + (size_t)j0 * RR;
    float acc[4] = {0.f, 0.f, 0.f, 0.f};
#pragma unroll
    for (int k = 0; k < RR; k++) {
        float av = d_aT[k * BB + b];
#pragma unroll
        for (int q = 0; q < 4; q++)
            acc[q] = fmaf(av, w[q * RR + k], acc[q]);
    }
#pragma unroll
    for (int q = 0; q < 4; q++) {
        int j = j0 + q;
        float z = acc[q] + cab2[j];
        float h = d_h1T[j * BB + b];
        d_h2T[j * BB + b] = h / (1.0f + expf(-2.0f * z));  // sigmoid(a + a)
    }
}

// ---- kernel 5: h3 = GELU(BN(h2 @ w2^T + b2)), out [B][C] (B-major) ----
__global__ __launch_bounds__(256) void gemm2_kernel(
    const float* __restrict__ w2, const float* __restrict__ b2,
    const float* __restrict__ bg, const float* __restrict__ bb,
    const float* __restrict__ bm, const float* __restrict__ bv) {
    int b  = threadIdx.x;
    int j0 = blockIdx.x * 16 + threadIdx.y * 4;
    const float* w = w2 + (size_t)j0 * C2;
    float acc[4] = {0.f, 0.f, 0.f, 0.f};
#pragma unroll 4
    for (int k = 0; k < C2; k++) {
        float hv = d_h2T[k * BB + b];
#pragma unroll
        for (int q = 0; q < 4; q++)
            acc[q] = fmaf(hv, w[q * C2 + k], acc[q]);
    }
#pragma unroll
    for (int q = 0; q < 4; q++) {
        int j = j0 + q;
        float y = acc[q] + b2[j];
        y = (y - bm[j]) * rsqrtf(bv[j] + 1e-5f) * bg[j] + bb[j];
        d_h3[b * CC + j] = gelu_exact(y);
    }
}

// ---- kernel 6: scores = h3 @ w3^T + b3 ; top-2 ; softmax(vals/2) ----
// one block per batch row; warp e computes score[e].
__global__ __launch_bounds__(512) void scores_topk_kernel(
    const float* __restrict__ w3, const float* __restrict__ b3,
    float* __restrict__ out) {
    int b    = blockIdx.x;
    int e    = threadIdx.x >> 5;
    int lane = threadIdx.x & 31;
    const float* h = d_h3 + b * CC;
    const float* w = w3 + e * CC;
    float s = 0.f;
#pragma unroll
    for (int i = 0; i < CC / 32; i++) {
        int k = lane + 32 * i;
        s = fmaf(h[k], w[k], s);
    }
#pragma unroll
    for (int o = 16; o; o >>= 1) s += __shfl_xor_sync(0xffffffffu, s, o);
    __shared__ float sc[EE];
    if (lane == 0) sc[e] = s + b3[e];
    __syncthreads();
    if (threadIdx.x == 0) {
        // top-1 (lowest index on ties, matching jax.lax.top_k)
        int i0 = 0; float v0 = sc[0];
#pragma unroll
        for (int t = 1; t < EE; t++) { if (sc[t] > v0) { v0 = sc[t]; i0 = t; } }
        // top-2 excluding i0
        int i1 = -1; float v1 = -3.402823466e38f;
#pragma unroll
        for (int t = 0; t < EE; t++) {
            if (t != i0 && sc[t] > v1) { v1 = sc[t]; i1 = t; }
        }
        // softmax([v0, v1] / 2); v0 >= v1 so it's numerically safe
        float e1  = expf((v1 - v0) * 0.5f);
        float inv = 1.0f / (1.0f + e1);
        // output layout: idx (as float) flattened first, then probs
        out[b * 2 + 0]       = (float)i0;
        out[b * 2 + 1]       = (float)i1;
        out[128 + b * 2 + 0] = inv;
        out[128 + b * 2 + 1] = e1 * inv;
    }
}

extern "C" void kernel_launch(void* const* d_in, const int* in_sizes, int n_in,
                              void* d_out, int out_size) {
    const float* x     = (const float*)d_in[0];
    const float* w1    = (const float*)d_in[1];
    const float* b1    = (const float*)d_in[2];
    const float* bn1_g = (const float*)d_in[3];
    const float* bn1_b = (const float*)d_in[4];
    const float* bn1_m = (const float*)d_in[5];
    const float* bn1_v = (const float*)d_in[6];
    const float* caw1  = (const float*)d_in[7];
    const float* cab1  = (const float*)d_in[8];
    const float* caw2  = (const float*)d_in[9];
    const float* cab2  = (const float*)d_in[10];
    const float* w2    = (const float*)d_in[11];
    const float* b2    = (const float*)d_in[12];
    const float* bn2_g = (const float*)d_in[13];
    const float* bn2_b = (const float*)d_in[14];
    const float* bn2_m = (const float*)d_in[15];
    const float* bn2_v = (const float*)d_in[16];
    const float* w3    = (const float*)d_in[17];
    const float* b3    = (const float*)d_in[18];

    // 64*768 rows, one warp each, 8 warps per 256-thread block
    pool_kernel<<<(BB * CC) / 8, 256>>>((const float4*)x);
    gemm1_kernel<<<C2 / 16, dim3(64, 4)>>>(w1, b1, bn1_g, bn1_b, bn1_m, bn1_v);
    ca1_kernel<<<RR / 16, dim3(64, 4)>>>(caw1, cab1);
    ca2_kernel<<<C2 / 16, dim3(64, 4)>>>(caw2, cab2);
    gemm2_kernel<<<CC / 16, dim3(64, 4)>>>(w2, b2, bn2_g, bn2_b, bn2_m, bn2_v);
    scores_topk_kernel<<<BB, 512>>>(w3, b3, (float*)d_out);
}

// round 2
// speedup vs baseline: 3.0883x; 3.0883x over previous
#include <cuda_runtime.h>
#include <math.h>

#define BB 64
#define CC 768
#define C2 1536
#define RR 96
#define EE 16
#define KSPLIT 8

// ---- scratch (device globals; no allocations allowed) ----
__device__ float d_gT[CC * BB];          // pooled, transposed [C][B]
__device__ float d_h1T[C2 * BB];         // after conv1+BN+GELU, [2C][B]
__device__ float d_pa[KSPLIT * RR * BB]; // ca1 split-K partials
__device__ float d_aT[RR * BB];          // CA bottleneck, [R][B]
__device__ float d_h2T[C2 * BB];         // after gating, [2C][B]
__device__ float d_h3[BB * CC];          // after conv2+BN+GELU, [B][C]

__device__ __forceinline__ float gelu_exact(float z) {
    return 0.5f * z * (1.0f + erff(z * 0.7071067811865476f));
}

// ---- kernel 1: global average pool, x[B,C,H,W] -> gT[C][B] ----
__global__ __launch_bounds__(256) void pool_kernel(const float4* __restrict__ x) {
    int gid  = blockIdx.x * 256 + threadIdx.x;
    int warp = gid >> 5;
    int lane = gid & 31;
    const float4* p = x + (size_t)warp * 256 + lane;
    float s = 0.f;
#pragma unroll
    for (int k = 0; k < 8; k++) {
        float4 v = p[32 * k];
        s += (v.x + v.y) + (v.z + v.w);
    }
#pragma unroll
    for (int o = 16; o; o >>= 1) s += __shfl_xor_sync(0xffffffffu, s, o);
    if (lane == 0) {
        int b = warp / CC;
        int c = warp - b * CC;
        d_gT[c * BB + b] = s * (1.0f / 1024.0f);
    }
}

// dot of one weight row (float4-vectorized) against K-major activations,
// 4 independent accumulator chains; N4 = K/4 float4's, assumed % 4 == 0.
template<int N4, int UNROLL>
__device__ __forceinline__ float dot_kmajor(const float4* __restrict__ w4,
                                            const float* __restrict__ actT,
                                            int b) {
    float a0 = 0.f, a1 = 0.f, a2 = 0.f, a3 = 0.f;
#pragma unroll UNROLL
    for (int t = 0; t < N4 / 4; t++) {
        int k4 = t * 4;
        float4 wa = w4[k4 + 0];
        float4 wb = w4[k4 + 1];
        float4 wc = w4[k4 + 2];
        float4 wd = w4[k4 + 3];
        const float* g = actT + (k4 * 4) * BB + b;
        a0 = fmaf(g[ 0 * BB], wa.x, a0); a0 = fmaf(g[ 1 * BB], wa.y, a0);
        a0 = fmaf(g[ 2 * BB], wa.z, a0); a0 = fmaf(g[ 3 * BB], wa.w, a0);
        a1 = fmaf(g[ 4 * BB], wb.x, a1); a1 = fmaf(g[ 5 * BB], wb.y, a1);
        a1 = fmaf(g[ 6 * BB], wb.z, a1); a1 = fmaf(g[ 7 * BB], wb.w, a1);
        a2 = fmaf(g[ 8 * BB], wc.x, a2); a2 = fmaf(g[ 9 * BB], wc.y, a2);
        a2 = fmaf(g[10 * BB], wc.z, a2); a2 = fmaf(g[11 * BB], wc.w, a2);
        a3 = fmaf(g[12 * BB], wd.x, a3); a3 = fmaf(g[13 * BB], wd.y, a3);
        a3 = fmaf(g[14 * BB], wd.z, a3); a3 = fmaf(g[15 * BB], wd.w, a3);
    }
    return (a0 + a1) + (a2 + a3);
}

// ---- kernel 2: h1 = GELU(BN(g @ w1^T + b1)), out [2C][B] ----
// grid 384, block (64,4): thread = (b, j), j = bx*4+ty
__global__ __launch_bounds__(256) void gemm1_kernel(
    const float* __restrict__ w1, const float* __restrict__ b1,
    const float* __restrict__ bg, const float* __restrict__ bb,
    const float* __restrict__ bm, const float* __restrict__ bv) {
    int b = threadIdx.x;
    int j = blockIdx.x * 4 + threadIdx.y;
    float acc = dot_kmajor<CC / 4, 2>((const float4*)(w1 + (size_t)j * CC), d_gT, b);
    float y = acc + b1[j];
    y = (y - bm[j]) * rsqrtf(bv[j] + 1e-5f) * bg[j] + bb[j];
    d_h1T[j * BB + b] = gelu_exact(y);
}

// ---- kernel 3a: ca1 split-K partials: pa[ks][j][b] = partial dot ----
// grid (24, 8), block (64,4)
__global__ __launch_bounds__(256) void ca1_kernel(const float* __restrict__ caw1) {
    int b  = threadIdx.x;
    int j  = blockIdx.x * 4 + threadIdx.y;
    int ks = blockIdx.y;
    const int KC = C2 / KSPLIT;  // 192
    const float4* w4 = (const float4*)(caw1 + (size_t)j * C2 + ks * KC);
    const float* act = d_h1T + ks * KC * BB;
    float acc = dot_kmajor<KC / 4, 2>(w4, act, b);
    d_pa[(ks * RR + j) * BB + b] = acc;
}

// ---- kernel 3b: reduce partials + bias + GELU -> aT[j][b] ----
__global__ __launch_bounds__(256) void ca1_epi_kernel(const float* __restrict__ cab1) {
    int tid = blockIdx.x * 256 + threadIdx.x;  // j*64+b, 6144 total
    float s = 0.f;
#pragma unroll
    for (int ks = 0; ks < KSPLIT; ks++) s += d_pa[ks * (RR * BB) + tid];
    int j = tid / BB;
    d_aT[tid] = gelu_exact(s + cab1[j]);
}

// ---- kernel 4: z = a @ caw2^T + cab2 ; h2 = h1 * sigmoid(2z) ----
// grid 384, block (64,4)
__global__ __launch_bounds__(256) void ca2_kernel(
    const float* __restrict__ caw2, const float* __restrict__ cab2) {
    int b = threadIdx.x;
    int j = blockIdx.x * 4 + threadIdx.y;
    float acc = dot_kmajor<RR / 4, 6>((const float4*)(caw2 + (size_t)j * RR), d_aT, b);
    float z = acc + cab2[j];
    float h = d_h1T[j * BB + b];
    d_h2T[j * BB + b] = h / (1.0f + expf(-2.0f * z));
}

// ---- kernel 5: h3 = GELU(BN(h2 @ w2^T + b2)), out [B][C] ----
// grid 192, block (64,4)
__global__ __launch_bounds__(256) void gemm2_kernel(
    const float* __restrict__ w2, const float* __restrict__ b2,
    const float* __restrict__ bg, const float* __restrict__ bb,
    const float* __restrict__ bm, const float* __restrict__ bv) {
    int b = threadIdx.x;
    int j = blockIdx.x * 4 + threadIdx.y;
    float acc = dot_kmajor<C2 / 4, 2>((const float4*)(w2 + (size_t)j * C2), d_h2T, b);
    float y = acc + b2[j];
    y = (y - bm[j]) * rsqrtf(bv[j] + 1e-5f) * bg[j] + bb[j];
    d_h3[b * CC + j] = gelu_exact(y);
}

// ---- kernel 6: scores = h3 @ w3^T + b3 ; top-2 ; softmax(vals/2) ----
__global__ __launch_bounds__(512) void scores_topk_kernel(
    const float* __restrict__ w3, const float* __restrict__ b3,
    float* __restrict__ out) {
    int b    = blockIdx.x;
    int e    = threadIdx.x >> 5;
    int lane = threadIdx.x & 31;
    const float* h = d_h3 + b * CC;
    const float* w = w3 + e * CC;
    float s = 0.f;
#pragma unroll
    for (int i = 0; i < CC / 32; i++) {
        int k = lane + 32 * i;
        s = fmaf(h[k], w[k], s);
    }
#pragma unroll
    for (int o = 16; o; o >>= 1) s += __shfl_xor_sync(0xffffffffu, s, o);
    __shared__ float sc[EE];
    if (lane == 0) sc[e] = s + b3[e];
    __syncthreads();
    if (threadIdx.x == 0) {
        int i0 = 0; float v0 = sc[0];
#pragma unroll
        for (int t = 1; t < EE; t++) { if (sc[t] > v0) { v0 = sc[t]; i0 = t; } }
        int i1 = -1; float v1 = -3.402823466e38f;
#pragma unroll
        for (int t = 0; t < EE; t++) {
            if (t != i0 && sc[t] > v1) { v1 = sc[t]; i1 = t; }
        }
        float e1  = expf((v1 - v0) * 0.5f);
        float inv = 1.0f / (1.0f + e1);
        out[b * 2 + 0]       = (float)i0;
        out[b * 2 + 1]       = (float)i1;
        out[128 + b * 2 + 0] = inv;
        out[128 + b * 2 + 1] = e1 * inv;
    }
}

extern "C" void kernel_launch(void* const* d_in, const int* in_sizes, int n_in,
                              void* d_out, int out_size) {
    const float* x     = (const float*)d_in[0];
    const float* w1    = (const float*)d_in[1];
    const float* b1    = (const float*)d_in[2];
    const float* bn1_g = (const float*)d_in[3];
    const float* bn1_b = (const float*)d_in[4];
    const float* bn1_m = (const float*)d_in[5];
    const float* bn1_v = (const float*)d_in[6];
    const float* caw1  = (const float*)d_in[7];
    const float* cab1  = (const float*)d_in[8];
    const float* caw2  = (const float*)d_in[9];
    const float* cab2  = (const float*)d_in[10];
    const float* w2    = (const float*)d_in[11];
    const float* b2    = (const float*)d_in[12];
    const float* bn2_g = (const float*)d_in[13];
    const float* bn2_b = (const float*)d_in[14];
    const float* bn2_m = (const float*)d_in[15];
    const float* bn2_v = (const float*)d_in[16];
    const float* w3    = (const float*)d_in[17];
    const float* b3    = (const float*)d_in[18];

    pool_kernel<<<(BB * CC) / 8, 256>>>((const float4*)x);
    gemm1_kernel<<<C2 / 4, dim3(64, 4)>>>(w1, b1, bn1_g, bn1_b, bn1_m, bn1_v);
    ca1_kernel<<<dim3(RR / 4, KSPLIT), dim3(64, 4)>>>(caw1);
    ca1_epi_kernel<<<(RR * BB) / 256, 256>>>(cab1);
    ca2_kernel<<<C2 / 4, dim3(64, 4)>>>(caw2, cab2);
    gemm2_kernel<<<CC / 4, dim3(64, 4)>>>(w2, b2, bn2_g, bn2_b, bn2_m, bn2_v);
    scores_topk_kernel<<<BB, 512>>>(w3, b3, (float*)d_out);
}

// round 3
// speedup vs baseline: 5.5331x; 1.7916x over previous
#include <cuda_runtime.h>
#include <math.h>

#define BB 64
#define CC 768
#define C2 1536
#define RR 96
#define EE 16

// ---- scratch (device globals) ----
__device__ float d_gT[CC * BB];        // pooled, [C][B]
__device__ float d_p1[6 * C2 * BB];    // gemm1 split-K partials
__device__ float d_h1T[C2 * BB];       // conv1+BN+GELU, [2C][B]
__device__ float d_pa[12 * RR * BB];   // ca1 split-K partials
__device__ float d_aT[RR * BB];        // bottleneck, [R][B]
__device__ float d_h2T[C2 * BB];       // gated, [2C][B]
__device__ float d_p2[12 * CC * BB];   // gemm2 split-K partials
__device__ float d_h3[BB * CC];        // conv2+BN+GELU, [B][C]
__device__ unsigned long long g_bar;   // monotonic barrier ticket counter

__device__ __forceinline__ float gelu_exact(float z) {
    return 0.5f * z * (1.0f + erff(z * 0.7071067811865476f));
}
__device__ __forceinline__ float sig2(float z) {          // sigmoid(2z)
    return 1.0f / (1.0f + expf(-2.0f * z));
}

// grid-wide barrier: monotonic ticket counter, safe across graph replays
// (counter never resets; target is next multiple of nb above my ticket).
__device__ __forceinline__ void gbar(int nb) {
    __syncthreads();
    if (threadIdx.x == 0) {
        __threadfence();
        unsigned long long t = atomicAdd(&g_bar, 1ULL);
        unsigned long long tgt = (t / (unsigned long long)nb + 1ULL) * (unsigned long long)nb;
        while (atomicAdd(&g_bar, 0ULL) < tgt) __nanosleep(64);
    }
    __syncthreads();
}

// tiled partial GEMM: JT output channels (j0..j0+JT), k-range [k0, k0+kcnt),
// act K-major [K][64]; W row-major [N][ldw]. Thread tile: 4 b x NJ j.
// smem: s_act[KC][64], s_w[JT][KC+4]. JT = 16*NJ. kcnt % KC == 0.
template<int JT, int NJ, int KC>
__device__ __forceinline__ void tile_mm(
    const float* __restrict__ W, int ldw,
    const float* __restrict__ actT,
    int j0, int k0, int kcnt,
    float4* acc, float* s_act, float* s_w) {
    const int tid = threadIdx.x;
    const int bg = tid & 15, jg = tid >> 4;
    for (int kk = 0; kk < kcnt; kk += KC) {
        // load act chunk [KC][64] (contiguous copy)
        const float4* a4 = (const float4*)(actT + (k0 + kk) * BB);
        float4* sa4 = (float4*)s_act;
        for (int i = tid; i < KC * 16; i += 256) sa4[i] = a4[i];
        // load w chunk [JT][KC], row pitch KC+4
        const float4* w4g = (const float4*)W;
        for (int f = tid; f < JT * (KC / 4); f += 256) {
            int j = f / (KC / 4), kq = f % (KC / 4);
            float4 v = w4g[((j0 + j) * ldw + k0 + kk) / 4 + kq];
            *(float4*)(s_w + j * (KC + 4) + kq * 4) = v;
        }
        __syncthreads();
        const float* aw = s_w + (jg * NJ) * (KC + 4);
#pragma unroll 4
        for (int k = 0; k < KC; k++) {
            float4 a = *(const float4*)(s_act + k * BB + bg * 4);
#pragma unroll
            for (int q = 0; q < NJ; q++) {
                float w = aw[q * (KC + 4) + k];
                acc[q].x = fmaf(a.x, w, acc[q].x);
                acc[q].y = fmaf(a.y, w, acc[q].y);
                acc[q].z = fmaf(a.z, w, acc[q].z);
                acc[q].w = fmaf(a.w, w, acc[q].w);
            }
        }
        __syncthreads();
    }
}

__global__ __launch_bounds__(256) void fused_kernel(
    const float4* __restrict__ x,
    const float* __restrict__ w1,   const float* __restrict__ b1,
    const float* __restrict__ bn1g, const float* __restrict__ bn1b,
    const float* __restrict__ bn1m, const float* __restrict__ bn1v,
    const float* __restrict__ caw1, const float* __restrict__ cab1,
    const float* __restrict__ caw2, const float* __restrict__ cab2,
    const float* __restrict__ w2,   const float* __restrict__ b2,
    const float* __restrict__ bn2g, const float* __restrict__ bn2b,
    const float* __restrict__ bn2m, const float* __restrict__ bn2v,
    const float* __restrict__ w3,   const float* __restrict__ b3,
    float* __restrict__ out, int nb) {
    __shared__ float s_act[96 * 64];   // 24 KB
    __shared__ float s_w[64 * 68];     // 17 KB
    __shared__ float s_sc[EE];
    const int tid = threadIdx.x;
    const int bg = tid & 15, jg = tid >> 4;

    // ---- stage 0: global average pool -> gT[C][B] ----
    {
        int warp = blockIdx.x * 8 + (tid >> 5);
        int lane = tid & 31;
        for (int r = warp; r < BB * CC; r += nb * 8) {
            const float4* p = x + (size_t)r * 256 + lane;
            float s = 0.f;
#pragma unroll
            for (int k = 0; k < 8; k++) {
                float4 v = p[32 * k];
                s += (v.x + v.y) + (v.z + v.w);
            }
#pragma unroll
            for (int o = 16; o; o >>= 1) s += __shfl_xor_sync(0xffffffffu, s, o);
            if (lane == 0) {
                int b = r / CC, c = r - b * CC;
                d_gT[c * BB + b] = s * (1.0f / 1024.0f);
            }
        }
    }
    gbar(nb);

    // ---- stage 1: gemm1 partials (24 j-tiles x 6 k-slices = 144 items) ----
    for (int it = blockIdx.x; it < 144; it += nb) {
        int jt = it % 24, ks = it / 24;
        float4 acc[4] = {};
        tile_mm<64, 4, 64>(w1, CC, d_gT, jt * 64, ks * 128, 128, acc, s_act, s_w);
#pragma unroll
        for (int q = 0; q < 4; q++) {
            int j = jt * 64 + jg * 4 + q;
            *(float4*)(d_p1 + (ks * C2 + j) * BB + bg * 4) = acc[q];
        }
    }
    gbar(nb);

    // ---- stage 2: reduce + BN + GELU -> h1T ----
    for (int idx = blockIdx.x * 256 + tid; idx < C2 * BB; idx += nb * 256) {
        float s = 0.f;
#pragma unroll
        for (int k = 0; k < 6; k++) s += d_p1[k * C2 * BB + idx];
        int j = idx >> 6;
        float y = s + b1[j];
        y = (y - bn1m[j]) * rsqrtf(bn1v[j] + 1e-5f) * bn1g[j] + bn1b[j];
        d_h1T[idx] = gelu_exact(y);
    }
    gbar(nb);

    // ---- stage 3: ca1 partials (3 j-tiles x 12 k-slices = 36 items) ----
    for (int it = blockIdx.x; it < 36; it += nb) {
        int jt = it % 3, ks = it / 3;
        float4 acc[2] = {};
        tile_mm<32, 2, 64>(caw1, C2, d_h1T, jt * 32, ks * 128, 128, acc, s_act, s_w);
#pragma unroll
        for (int q = 0; q < 2; q++) {
            int j = jt * 32 + jg * 2 + q;
            *(float4*)(d_pa + (ks * RR + j) * BB + bg * 4) = acc[q];
        }
    }
    gbar(nb);

    // ---- stage 4: reduce + GELU -> aT ----
    for (int idx = blockIdx.x * 256 + tid; idx < RR * BB; idx += nb * 256) {
        float s = 0.f;
#pragma unroll
        for (int k = 0; k < 12; k++) s += d_pa[k * RR * BB + idx];
        int j = idx >> 6;
        d_aT[idx] = gelu_exact(s + cab1[j]);
    }
    gbar(nb);

    // ---- stage 5: ca2 (K=96, no split) + sigmoid gating -> h2T (48 items) ----
    for (int it = blockIdx.x; it < 48; it += nb) {
        int j0 = it * 32;
        float4 acc[2] = {};
        tile_mm<32, 2, 96>(caw2, RR, d_aT, j0, 0, 96, acc, s_act, s_w);
#pragma unroll
        for (int q = 0; q < 2; q++) {
            int j = j0 + jg * 2 + q;
            float bias = cab2[j];
            float4 h = *(const float4*)(d_h1T + j * BB + bg * 4);
            float4 o;
            o.x = h.x * sig2(acc[q].x + bias);
            o.y = h.y * sig2(acc[q].y + bias);
            o.z = h.z * sig2(acc[q].z + bias);
            o.w = h.w * sig2(acc[q].w + bias);
            *(float4*)(d_h2T + j * BB + bg * 4) = o;
        }
    }
    gbar(nb);

    // ---- stage 6: gemm2 partials (12 j-tiles x 12 k-slices = 144 items) ----
    for (int it = blockIdx.x; it < 144; it += nb) {
        int jt = it % 12, ks = it / 12;
        float4 acc[4] = {};
        tile_mm<64, 4, 64>(w2, C2, d_h2T, jt * 64, ks * 128, 128, acc, s_act, s_w);
#pragma unroll
        for (int q = 0; q < 4; q++) {
            int j = jt * 64 + jg * 4 + q;
            *(float4*)(d_p2 + (ks * CC + j) * BB + bg * 4) = acc[q];
        }
    }
    gbar(nb);

    // ---- stage 7: reduce + BN + GELU -> h3 [B][C] ----
    for (int idx = blockIdx.x * 256 + tid; idx < CC * BB; idx += nb * 256) {
        float s = 0.f;
#pragma unroll
        for (int k = 0; k < 12; k++) s += d_p2[k * CC * BB + idx];
        int j = idx >> 6, b = idx & 63;
        float y = s + b2[j];
        y = (y - bn2m[j]) * rsqrtf(bn2v[j] + 1e-5f) * bn2g[j] + bn2b[j];
        d_h3[b * CC + j] = gelu_exact(y);
    }
    gbar(nb);

    // ---- stage 8: scores + top-2 + softmax ----
    for (int b = blockIdx.x; b < BB; b += nb) {
        int w = tid >> 5, lane = tid & 31;
        const float* h = d_h3 + b * CC;
#pragma unroll
        for (int q = 0; q < 2; q++) {
            int e = w + 8 * q;
            const float* wr = w3 + e * CC;
            float s = 0.f;
#pragma unroll
            for (int i = 0; i < CC / 32; i++) {
                int k = lane + 32 * i;
                s = fmaf(h[k], wr[k], s);
            }
#pragma unroll
            for (int o = 16; o; o >>= 1) s += __shfl_xor_sync(0xffffffffu, s, o);
            if (lane == 0) s_sc[e] = s + b3[e];
        }
        __syncthreads();
        if (tid == 0) {
            int i0 = 0; float v0 = s_sc[0];
#pragma unroll
            for (int t = 1; t < EE; t++) { if (s_sc[t] > v0) { v0 = s_sc[t]; i0 = t; } }
            int i1 = -1; float v1 = -3.402823466e38f;
#pragma unroll
            for (int t = 0; t < EE; t++) {
                if (t != i0 && s_sc[t] > v1) { v1 = s_sc[t]; i1 = t; }
            }
            float e1  = expf((v1 - v0) * 0.5f);
            float inv = 1.0f / (1.0f + e1);
            out[b * 2 + 0]       = (float)i0;
            out[b * 2 + 1]       = (float)i1;
            out[128 + b * 2 + 0] = inv;
            out[128 + b * 2 + 1] = e1 * inv;
        }
        __syncthreads();
    }
}

extern "C" void kernel_launch(void* const* d_in, const int* in_sizes, int n_in,
                              void* d_out, int out_size) {
    const float* x     = (const float*)d_in[0];
    const float* w1    = (const float*)d_in[1];
    const float* b1    = (const float*)d_in[2];
    const float* bn1_g = (const float*)d_in[3];
    const float* bn1_b = (const float*)d_in[4];
    const float* bn1_m = (const float*)d_in[5];
    const float* bn1_v = (const float*)d_in[6];
    const float* caw1  = (const float*)d_in[7];
    const float* cab1  = (const float*)d_in[8];
    const float* caw2  = (const float*)d_in[9];
    const float* cab2  = (const float*)d_in[10];
    const float* w2    = (const float*)d_in[11];
    const float* b2    = (const float*)d_in[12];
    const float* bn2_g = (const float*)d_in[13];
    const float* bn2_b = (const float*)d_in[14];
    const float* bn2_m = (const float*)d_in[15];
    const float* bn2_v = (const float*)d_in[16];
    const float* w3    = (const float*)d_in[17];
    const float* b3    = (const float*)d_in[18];

    int nsm = 148;
    cudaDeviceGetAttribute(&nsm, cudaDevAttrMultiProcessorCount, 0);

    fused_kernel<<<nsm, 256>>>((const float4*)x,
        w1, b1, bn1_g, bn1_b, bn1_m, bn1_v,
        caw1, cab1, caw2, cab2,
        w2, b2, bn2_g, bn2_b, bn2_m, bn2_v,
        w3, b3, (float*)d_out, nsm);
}